// round 15
// baseline (speedup 1.0000x reference)
#include <cuda_runtime.h>
#include <cuda_fp16.h>
#include <cstdint>

#define N_USERS 50000
#define NNODES  200000
#define NEDGES  1250000
#define NLAYERS 3
#define NSCANB  196            // ceil(200000/1024)

// ---------------------------------------------------------------- scratch globals
__device__ int   g_cursor[NNODES];            // degree, then fill cursor
__device__ int   g_rowptr[NNODES + 1];        // CSR row pointers
__device__ int   g_bsum[256];                 // scan block sums
__device__ int2  g_csre[NEDGES];              // CSR packed (src, weight bits)
__device__ uint4 g_Wbf[3 * 1536];             // preconverted W (fp16), swizzled layout
__device__ float g_bias[3 * 64];              // combined bias per layer
__device__ uint2 g_e16[2][(size_t)NNODES * 16]; // fp16 embedding mirror, ping-pong

// ---------------------------------------------------------------- layout helpers
// A rows: 384B = 24 chunks fp16 of [t1 | t1*e | e]
// W rows: 384B = 24 chunks fp16
#define ROW_B    384
#define SM_A     0        // 64 * 384 = 24576
#define SM_W     24576    // 64 * 384 = 24576
#define SM_BIAS  49152    // 64 floats
#define SM_TOTAL 49408
#define OPITCH   68       // epilogue f32 staging pitch (floats)

__device__ __forceinline__ uint32_t swz_c(int row, int c) {   // 16B chunk address
    return (uint32_t)row * ROW_B + ((((uint32_t)c) ^ ((uint32_t)row & 7)) << 4);
}

__device__ __forceinline__ void cvt_pack8h_hi(const float* x, uint32_t* hp) {
    #pragma unroll
    for (int j = 0; j < 4; j++) {
        __half2 hh = __halves2half2(__float2half_rn(x[2 * j]), __float2half_rn(x[2 * j + 1]));
        hp[j] = *(uint32_t*)&hh;
    }
}

__device__ __forceinline__ uint32_t pack2h(float a, float b) {
    __half2 hh = __halves2half2(__float2half_rn(a), __float2half_rn(b));
    return *(uint32_t*)&hh;
}

__device__ __forceinline__ float2 h2f2(uint32_t u) {
    __half2 h = *(__half2*)&u;
    return __half22float2(h);
}

__device__ __forceinline__ void ldm_x4(uint32_t& r0, uint32_t& r1, uint32_t& r2,
                                       uint32_t& r3, uint32_t addr) {
    asm volatile("ldmatrix.sync.aligned.m8n8.x4.shared.b16 {%0,%1,%2,%3}, [%4];"
                 : "=r"(r0), "=r"(r1), "=r"(r2), "=r"(r3) : "r"(addr));
}

// ---------------------------------------------------------------- init: e0 (+fp16 mirror) + zero cursor
__global__ void init_kernel(const float4* __restrict__ u4, const float4* __restrict__ i4,
                            float4* __restrict__ out4) {
    int i = blockIdx.x * blockDim.x + threadIdx.x;
    if (i >= NNODES * 16) return;
    int row = i >> 4, q = i & 15;
    float4 v = (row < N_USERS) ? u4[row * 16 + q] : i4[(row - N_USERS) * 16 + q];
    out4[(size_t)row * 64 + q] = v;
    g_e16[0][i] = make_uint2(pack2h(v.x, v.y), pack2h(v.z, v.w));
    if (i < NNODES) g_cursor[i] = 0;
}

// ---------------------------------------------------------------- CSR build
__global__ void hist_kernel(const int* __restrict__ dst) {
    int e = blockIdx.x * blockDim.x + threadIdx.x;
    if (e < NEDGES) atomicAdd(&g_cursor[dst[e]], 1);
}

// block-local exclusive scan; per-block totals to g_bsum
__global__ void scan1_kernel() {
    __shared__ int wsum[32];
    const unsigned FULL = 0xffffffffu;
    int tid = threadIdx.x, lane = tid & 31, wid = tid >> 5;
    int idx = blockIdx.x * 1024 + tid;
    int v = (idx < NNODES) ? g_cursor[idx] : 0;
    int inc = v;
    #pragma unroll
    for (int o = 1; o < 32; o <<= 1) {
        int t = __shfl_up_sync(FULL, inc, o);
        if (lane >= o) inc += t;
    }
    if (lane == 31) wsum[wid] = inc;
    __syncthreads();
    if (wid == 0) {
        int s = wsum[lane];
        #pragma unroll
        for (int o = 1; o < 32; o <<= 1) {
            int t = __shfl_up_sync(FULL, s, o);
            if (lane >= o) s += t;
        }
        wsum[lane] = s;
    }
    __syncthreads();
    int excl = (wid ? wsum[wid - 1] : 0) + inc - v;
    if (idx < NNODES) g_rowptr[idx] = excl;
    if (tid == 0) g_bsum[blockIdx.x] = wsum[31];
}

// exclusive scan of the NSCANB block sums (single block)
__global__ void scan2_kernel() {
    __shared__ int ws[8];
    const unsigned FULL = 0xffffffffu;
    int t = threadIdx.x, lane = t & 31, wid = t >> 5;
    int v = (t < NSCANB) ? g_bsum[t] : 0;
    int inc = v;
    #pragma unroll
    for (int o = 1; o < 32; o <<= 1) {
        int x = __shfl_up_sync(FULL, inc, o);
        if (lane >= o) inc += x;
    }
    if (lane == 31) ws[wid] = inc;
    __syncthreads();
    if (wid == 0) {
        int s = (lane < 8) ? ws[lane] : 0;
        #pragma unroll
        for (int o = 1; o < 8; o <<= 1) {
            int x = __shfl_up_sync(FULL, s, o);
            if (lane >= o) s += x;
        }
        if (lane < 8) ws[lane] = s;
    }
    __syncthreads();
    int excl = (wid ? ws[wid - 1] : 0) + inc - v;
    __syncthreads();
    if (t < NSCANB) g_bsum[t] = excl;
}

// add block offsets; mirror to cursor
__global__ void scan3_kernel() {
    int idx = blockIdx.x * blockDim.x + threadIdx.x;
    if (idx < NNODES) {
        int rp = g_rowptr[idx] + g_bsum[idx >> 10];
        g_rowptr[idx] = rp;
        g_cursor[idx] = rp;
    }
    if (idx == 0) g_rowptr[NNODES] = NEDGES;
}

__global__ void fill_kernel(const int* __restrict__ src, const int* __restrict__ dst,
                            const float* __restrict__ w) {
    int e = blockIdx.x * blockDim.x + threadIdx.x;
    if (e >= NEDGES) return;
    int d = dst[e];
    int slot = atomicAdd(&g_cursor[d], 1);
    g_csre[slot] = make_int2(src[e], __float_as_int(w[e]));
}

// ---------------------------------------------------------------- W preconvert (fp16)
__global__ void prep_w_kernel(const float* __restrict__ Ws, const float* __restrict__ bs) {
    const int l   = blockIdx.x;
    const int tid = threadIdx.x;
    const float* Wg = Ws + (size_t)l * 12288;
    #pragma unroll 1
    for (int item = tid; item < 24 * 64; item += 256) {
        int n = item & 63;
        int c = item >> 6;                 // chunk 0..23  (k = c*8 .. c*8+7)
        float x[8];
        #pragma unroll
        for (int j = 0; j < 8; j++) {
            int kg = c * 8 + j;            // 0..191
            x[j] = Wg[(kg >> 6) * 4096 + (kg & 63) * 64 + n];
        }
        uint32_t hp[4];
        cvt_pack8h_hi(x, hp);
        g_Wbf[l * 1536 + (swz_c(n, c) >> 4)] = make_uint4(hp[0], hp[1], hp[2], hp[3]);
    }
    if (tid < 64) {
        const float* bg = bs + l * 192;
        g_bias[l * 64 + tid] = bg[tid] + bg[64 + tid] + bg[128 + tid];
    }
}

// ---------------------------------------------------------------- fused gather + GEMM
// 256 threads/CTA, 64-row tile, 4 CTAs/SM (49.4KB smem).
// Gather reads fp16 mirror g_e16[layer&1] (8B/edge/thread); epilogue writes
// g_e16[(layer+1)&1] (ping-pong kills the intra-kernel read/write race).
// Single-pass fp16 MMA: D = fl16(A) @ fl16(W)
__global__ __launch_bounds__(256, 4)
void ngcf_fused(const float* __restrict__ out_ro, float* __restrict__ out, int layer) {
    extern __shared__ __align__(128) char sm[];
    const int tid  = threadIdx.x;
    const int row0 = blockIdx.x * 64;     // 3125 * 64 == NNODES exactly
    const uint2* __restrict__ e16r = g_e16[layer & 1];
    uint2* __restrict__       e16w = g_e16[(layer + 1) & 1];

    // stage W: linear copy of preconverted, pre-swizzled layer slab (fp16)
    {
        const uint4* gw = g_Wbf + layer * 1536;
        uint4* sw = (uint4*)(sm + SM_W);
        #pragma unroll 2
        for (int i = tid; i < 1536; i += 256) sw[i] = gw[i];
    }
    if (tid < 64) ((float*)(sm + SM_BIAS))[tid] = g_bias[layer * 64 + tid];

    // ---- phase 1 (merged): gather t1 from fp16 mirror, build A blocks
    // chunks: [0..7] t1, [8..15] t1*e, [16..23] e
    {
        const float4* op = (const float4*)out_ro;
        #pragma unroll
        for (int j = 0; j < 4; j++) {
            int item = tid + 256 * j;          // 1024 items: (r, q)
            int r = item >> 4, q = item & 15;
            int n = row0 + r;
            int i0 = g_rowptr[n], i1 = g_rowptr[n + 1];
            float4 acc = make_float4(0.f, 0.f, 0.f, 0.f);
            int i = i0;
            for (; i + 3 < i1; i += 4) {
                int2 p0 = g_csre[i],     p1 = g_csre[i + 1];
                int2 p2 = g_csre[i + 2], p3 = g_csre[i + 3];
                uint2 u0 = e16r[(size_t)p0.x * 16 + q];
                uint2 u1 = e16r[(size_t)p1.x * 16 + q];
                uint2 u2 = e16r[(size_t)p2.x * 16 + q];
                uint2 u3 = e16r[(size_t)p3.x * 16 + q];
                float w0 = __int_as_float(p0.y), w1 = __int_as_float(p1.y);
                float w2 = __int_as_float(p2.y), w3 = __int_as_float(p3.y);
                float2 a0 = h2f2(u0.x), b0 = h2f2(u0.y);
                float2 a1 = h2f2(u1.x), b1 = h2f2(u1.y);
                float2 a2 = h2f2(u2.x), b2 = h2f2(u2.y);
                float2 a3 = h2f2(u3.x), b3 = h2f2(u3.y);
                acc.x += w0 * a0.x + w1 * a1.x + w2 * a2.x + w3 * a3.x;
                acc.y += w0 * a0.y + w1 * a1.y + w2 * a2.y + w3 * a3.y;
                acc.z += w0 * b0.x + w1 * b1.x + w2 * b2.x + w3 * b3.x;
                acc.w += w0 * b0.y + w1 * b1.y + w2 * b2.y + w3 * b3.y;
            }
            for (; i < i1; i++) {
                int2 p = g_csre[i];
                uint2 u = e16r[(size_t)p.x * 16 + q];
                float w0 = __int_as_float(p.y);
                float2 a = h2f2(u.x), b = h2f2(u.y);
                acc.x += w0 * a.x; acc.y += w0 * a.y;
                acc.z += w0 * b.x; acc.w += w0 * b.y;
            }
            // own e float4 (fp32, from out) for t1*e and e chunks
            float4 ev = op[(size_t)n * 64 + (size_t)layer * 16 + q];
            float4 t2 = make_float4(acc.x * ev.x, acc.y * ev.y,
                                    acc.z * ev.z, acc.w * ev.w);
            uint32_t half_off = (uint32_t)(q & 1) * 8;
            int c = q >> 1;
            *(uint2*)(sm + SM_A + swz_c(r, c) + half_off) =
                make_uint2(pack2h(acc.x, acc.y), pack2h(acc.z, acc.w));
            *(uint2*)(sm + SM_A + swz_c(r, 8 + c) + half_off) =
                make_uint2(pack2h(t2.x, t2.y), pack2h(t2.z, t2.w));
            *(uint2*)(sm + SM_A + swz_c(r, 16 + c) + half_off) =
                make_uint2(pack2h(ev.x, ev.y), pack2h(ev.z, ev.w));
        }
    }
    __syncthreads();

    // ---- phase 2: 8 warps = 2(m) x 4(n); warp tile 32(m) x 16(n); 12 k-steps
    const int wid = tid >> 5, lane = tid & 31;
    const int wm  = wid >> 2, wn = wid & 3;
    const uint32_t smA = (uint32_t)__cvta_generic_to_shared(sm) + SM_A;
    const uint32_t smW = (uint32_t)__cvta_generic_to_shared(sm) + SM_W;
    const uint32_t lr    = lane & 7;
    const uint32_t jlow  = (lane >> 3) & 1;
    const uint32_t jhigh = (lane >> 4) & 1;
    const uint32_t rowA0  = (uint32_t)wm * 32 + jlow * 8 + lr;
    const uint32_t baseA0 = smA + rowA0 * ROW_B;
    const uint32_t baseA1 = baseA0 + 16 * ROW_B;
    const uint32_t xA     = rowA0 & 7;
    const uint32_t rowW  = (uint32_t)wn * 16 + jhigh * 8 + lr;
    const uint32_t baseW = smW + rowW * ROW_B;
    const uint32_t xW    = rowW & 7;

    float acc[2][2][4];
    #pragma unroll
    for (int a = 0; a < 2; a++)
        #pragma unroll
        for (int b = 0; b < 2; b++)
            #pragma unroll
            for (int i = 0; i < 4; i++) acc[a][b][i] = 0.f;

    #pragma unroll
    for (int s = 0; s < 12; s++) {
        uint32_t cA = 2u * s + jhigh;
        uint32_t cW = 2u * s + jlow;
        uint32_t a0[4], a1[4], bw[4];
        ldm_x4(a0[0], a0[1], a0[2], a0[3], baseA0 + ((cA ^ xA) << 4));
        ldm_x4(a1[0], a1[1], a1[2], a1[3], baseA1 + ((cA ^ xA) << 4));
        ldm_x4(bw[0], bw[1], bw[2], bw[3], baseW  + ((cW ^ xW) << 4));
        #pragma unroll
        for (int nt = 0; nt < 2; nt++) {
            asm volatile(
                "mma.sync.aligned.m16n8k16.row.col.f32.f16.f16.f32 "
                "{%0,%1,%2,%3}, {%4,%5,%6,%7}, {%8,%9}, {%0,%1,%2,%3};"
                : "+f"(acc[0][nt][0]), "+f"(acc[0][nt][1]),
                  "+f"(acc[0][nt][2]), "+f"(acc[0][nt][3])
                : "r"(a0[0]), "r"(a0[1]), "r"(a0[2]), "r"(a0[3]),
                  "r"(bw[nt * 2]), "r"(bw[nt * 2 + 1]));
            asm volatile(
                "mma.sync.aligned.m16n8k16.row.col.f32.f16.f16.f32 "
                "{%0,%1,%2,%3}, {%4,%5,%6,%7}, {%8,%9}, {%0,%1,%2,%3};"
                : "+f"(acc[1][nt][0]), "+f"(acc[1][nt][1]),
                  "+f"(acc[1][nt][2]), "+f"(acc[1][nt][3])
                : "r"(a1[0]), "r"(a1[1]), "r"(a1[2]), "r"(a1[3]),
                  "r"(bw[nt * 2]), "r"(bw[nt * 2 + 1]));
        }
    }
    __syncthreads();   // A/W smem dead; reuse for f32 staging

    // ---- phase 3a: bias + leaky, frags -> smem [64][OPITCH]
    {
        float* smo = (float*)sm;
        const float* sbias = (const float*)(sm + SM_BIAS);
        const int g = lane >> 2, q = lane & 3;
        #pragma unroll
        for (int mt = 0; mt < 2; mt++) {
            #pragma unroll
            for (int nt = 0; nt < 2; nt++) {
                int col = wn * 16 + nt * 8 + q * 2;
                float b0 = sbias[col], b1 = sbias[col + 1];
                int r = wm * 32 + mt * 16 + g;
                float v0 = acc[mt][nt][0] + b0; v0 = (v0 >= 0.f) ? v0 : 0.01f * v0;
                float v1 = acc[mt][nt][1] + b1; v1 = (v1 >= 0.f) ? v1 : 0.01f * v1;
                float v2 = acc[mt][nt][2] + b0; v2 = (v2 >= 0.f) ? v2 : 0.01f * v2;
                float v3 = acc[mt][nt][3] + b1; v3 = (v3 >= 0.f) ? v3 : 0.01f * v3;
                *(float2*)(smo + r * OPITCH + col)       = make_float2(v0, v1);
                *(float2*)(smo + (r + 8) * OPITCH + col) = make_float2(v2, v3);
            }
        }
    }
    __syncthreads();

    // ---- phase 3b: L2-normalize + store fp32 out + fp16 mirror
    {
        const float* smo = (const float*)sm;
        int r = tid >> 2, h = tid & 3;
        int row = row0 + r;
        float4 v[4];
        float ssum = 0.f;
        #pragma unroll
        for (int i = 0; i < 4; i++) {
            v[i] = *(const float4*)(smo + r * OPITCH + h * 16 + i * 4);
            ssum += v[i].x * v[i].x + v[i].y * v[i].y + v[i].z * v[i].z + v[i].w * v[i].w;
        }
        ssum += __shfl_xor_sync(0xffffffffu, ssum, 1);
        ssum += __shfl_xor_sync(0xffffffffu, ssum, 2);
        float inv = 1.0f / fmaxf(sqrtf(ssum), 1e-12f);
        float4* o4 = (float4*)(out + (size_t)row * 256 + (size_t)(layer + 1) * 64 + h * 16);
        uint2*  m2 = e16w + (size_t)row * 16 + h * 4;
        #pragma unroll
        for (int i = 0; i < 4; i++) {
            float4 nv = make_float4(v[i].x * inv, v[i].y * inv, v[i].z * inv, v[i].w * inv);
            o4[i] = nv;
            m2[i] = make_uint2(pack2h(nv.x, nv.y), pack2h(nv.z, nv.w));
        }
    }
}

// ---------------------------------------------------------------- launch
extern "C" void kernel_launch(void* const* d_in, const int* in_sizes, int n_in,
                              void* d_out, int out_size) {
    const int*    edge_src = (const int*)d_in[0];
    const int*    edge_dst = (const int*)d_in[1];
    const float*  edge_w   = (const float*)d_in[2];
    const float4* u4       = (const float4*)d_in[3];
    const float4* i4       = (const float4*)d_in[4];
    const float*  Ws       = (const float*)d_in[5];
    const float*  bs       = (const float*)d_in[6];
    float*        out      = (float*)d_out;

    cudaFuncSetAttribute(ngcf_fused, cudaFuncAttributeMaxDynamicSharedMemorySize, SM_TOTAL);

    init_kernel<<<(NNODES * 16 + 255) / 256, 256>>>(u4, i4, (float4*)out);
    hist_kernel<<<(NEDGES + 255) / 256, 256>>>(edge_dst);
    scan1_kernel<<<NSCANB, 1024>>>();
    scan2_kernel<<<1, 256>>>();
    scan3_kernel<<<(NNODES + 255) / 256, 256>>>();
    fill_kernel<<<(NEDGES + 255) / 256, 256>>>(edge_src, edge_dst, edge_w);
    prep_w_kernel<<<3, 256>>>(Ws, bs);

    for (int l = 0; l < NLAYERS; l++) {
        ngcf_fused<<<NNODES / 64, 256, SM_TOTAL>>>(out, out, l);
    }
}

// round 16
// speedup vs baseline: 1.1511x; 1.1511x over previous
#include <cuda_runtime.h>
#include <cuda_fp16.h>
#include <cstdint>

#define N_USERS 50000
#define NNODES  200000
#define NEDGES  1250000
#define NLAYERS 3
#define NSCANB  196            // ceil(200000/1024)

// ---------------------------------------------------------------- scratch globals
// INVARIANT: g_cursor is all-zero at kernel_launch entry (zero-initialized at
// module load; re-zeroed by the layer-2 fused kernel at the end of every launch).
__device__ int   g_cursor[NNODES];            // degree, then fill cursor
__device__ int   g_rowptr[NNODES + 1];        // CSR row pointers
__device__ int   g_bsum[256];                 // scan block sums
__device__ int2  g_csre[NEDGES];              // CSR packed (src, weight bits)
__device__ uint4 g_Wbf[3 * 1536];             // preconverted W (fp16), swizzled layout
__device__ float g_bias[3 * 64];              // combined bias per layer

// ---------------------------------------------------------------- layout helpers
// A rows: 384B = 24 chunks fp16 of [t1 | t1*e | e]
// W rows: 384B = 24 chunks fp16
#define ROW_B    384
#define SM_A     0        // 64 * 384 = 24576
#define SM_W     24576    // 64 * 384 = 24576
#define SM_BIAS  49152    // 64 floats
#define SM_TOTAL 49408
#define OPITCH   68       // epilogue f32 staging pitch (floats)

__device__ __forceinline__ uint32_t swz_c(int row, int c) {   // 16B chunk address
    return (uint32_t)row * ROW_B + ((((uint32_t)c) ^ ((uint32_t)row & 7)) << 4);
}

__device__ __forceinline__ void cvt_pack8h_hi(const float* x, uint32_t* hp) {
    #pragma unroll
    for (int j = 0; j < 4; j++) {
        __half2 hh = __halves2half2(__float2half_rn(x[2 * j]), __float2half_rn(x[2 * j + 1]));
        hp[j] = *(uint32_t*)&hh;
    }
}

__device__ __forceinline__ uint32_t pack2h(float a, float b) {
    __half2 hh = __halves2half2(__float2half_rn(a), __float2half_rn(b));
    return *(uint32_t*)&hh;
}

__device__ __forceinline__ void ldm_x4(uint32_t& r0, uint32_t& r1, uint32_t& r2,
                                       uint32_t& r3, uint32_t addr) {
    asm volatile("ldmatrix.sync.aligned.m8n8.x4.shared.b16 {%0,%1,%2,%3}, [%4];"
                 : "=r"(r0), "=r"(r1), "=r"(r2), "=r"(r3) : "r"(addr));
}

// ---------------------------------------------------------------- init: e0 + fused degree histogram
// g_cursor arrives all-zero (see invariant above), so the histogram can run in
// the same kernel as the embedding init — atomics hide under the copy traffic.
__global__ void init_hist_kernel(const float4* __restrict__ u4, const float4* __restrict__ i4,
                                 float4* __restrict__ out4, const int* __restrict__ dst) {
    int i = blockIdx.x * blockDim.x + threadIdx.x;
    if (i < NNODES * 16) {
        int row = i >> 4, q = i & 15;
        float4 v = (row < N_USERS) ? u4[row * 16 + q] : i4[(row - N_USERS) * 16 + q];
        out4[(size_t)row * 64 + q] = v;
    }
    if (i < NEDGES) atomicAdd(&g_cursor[dst[i]], 1);
}

// ---------------------------------------------------------------- CSR build
// block-local exclusive scan; per-block totals to g_bsum
__global__ void scan1_kernel() {
    __shared__ int wsum[32];
    const unsigned FULL = 0xffffffffu;
    int tid = threadIdx.x, lane = tid & 31, wid = tid >> 5;
    int idx = blockIdx.x * 1024 + tid;
    int v = (idx < NNODES) ? g_cursor[idx] : 0;
    int inc = v;
    #pragma unroll
    for (int o = 1; o < 32; o <<= 1) {
        int t = __shfl_up_sync(FULL, inc, o);
        if (lane >= o) inc += t;
    }
    if (lane == 31) wsum[wid] = inc;
    __syncthreads();
    if (wid == 0) {
        int s = wsum[lane];
        #pragma unroll
        for (int o = 1; o < 32; o <<= 1) {
            int t = __shfl_up_sync(FULL, s, o);
            if (lane >= o) s += t;
        }
        wsum[lane] = s;
    }
    __syncthreads();
    int excl = (wid ? wsum[wid - 1] : 0) + inc - v;
    if (idx < NNODES) g_rowptr[idx] = excl;
    if (tid == 0) g_bsum[blockIdx.x] = wsum[31];
}

// exclusive scan of the NSCANB block sums (single block)
__global__ void scan2_kernel() {
    __shared__ int ws[8];
    const unsigned FULL = 0xffffffffu;
    int t = threadIdx.x, lane = t & 31, wid = t >> 5;
    int v = (t < NSCANB) ? g_bsum[t] : 0;
    int inc = v;
    #pragma unroll
    for (int o = 1; o < 32; o <<= 1) {
        int x = __shfl_up_sync(FULL, inc, o);
        if (lane >= o) inc += x;
    }
    if (lane == 31) ws[wid] = inc;
    __syncthreads();
    if (wid == 0) {
        int s = (lane < 8) ? ws[lane] : 0;
        #pragma unroll
        for (int o = 1; o < 8; o <<= 1) {
            int x = __shfl_up_sync(FULL, s, o);
            if (lane >= o) s += x;
        }
        if (lane < 8) ws[lane] = s;
    }
    __syncthreads();
    int excl = (wid ? ws[wid - 1] : 0) + inc - v;
    __syncthreads();
    if (t < NSCANB) g_bsum[t] = excl;
}

// add block offsets; mirror to cursor
__global__ void scan3_kernel() {
    int idx = blockIdx.x * blockDim.x + threadIdx.x;
    if (idx < NNODES) {
        int rp = g_rowptr[idx] + g_bsum[idx >> 10];
        g_rowptr[idx] = rp;
        g_cursor[idx] = rp;
    }
    if (idx == 0) g_rowptr[NNODES] = NEDGES;
}

__global__ void fill_kernel(const int* __restrict__ src, const int* __restrict__ dst,
                            const float* __restrict__ w) {
    int e = blockIdx.x * blockDim.x + threadIdx.x;
    if (e >= NEDGES) return;
    int d = dst[e];
    int slot = atomicAdd(&g_cursor[d], 1);
    g_csre[slot] = make_int2(src[e], __float_as_int(w[e]));
}

// ---------------------------------------------------------------- W preconvert (fp16)
__global__ void prep_w_kernel(const float* __restrict__ Ws, const float* __restrict__ bs) {
    const int l   = blockIdx.x;
    const int tid = threadIdx.x;
    const float* Wg = Ws + (size_t)l * 12288;
    #pragma unroll 1
    for (int item = tid; item < 24 * 64; item += 256) {
        int n = item & 63;
        int c = item >> 6;                 // chunk 0..23  (k = c*8 .. c*8+7)
        float x[8];
        #pragma unroll
        for (int j = 0; j < 8; j++) {
            int kg = c * 8 + j;            // 0..191
            x[j] = Wg[(kg >> 6) * 4096 + (kg & 63) * 64 + n];
        }
        uint32_t hp[4];
        cvt_pack8h_hi(x, hp);
        g_Wbf[l * 1536 + (swz_c(n, c) >> 4)] = make_uint4(hp[0], hp[1], hp[2], hp[3]);
    }
    if (tid < 64) {
        const float* bg = bs + l * 192;
        g_bias[l * 64 + tid] = bg[tid] + bg[64 + tid] + bg[128 + tid];
    }
}

// ---------------------------------------------------------------- fused gather + GEMM
// 256 threads/CTA, 64-row tile, 4 CTAs/SM (49.4KB smem).
// Single-pass fp16 MMA: D = fl16(A) @ fl16(W)  (~3.6e-4 rel, gate is 1e-3)
// Phase 1 (merged): gather t1 (f32), load own e float4, build t1/t1*e/e fp16 chunks directly
// Phase 2: 12 k-steps mma.sync fp16, 8 warps 32x16 tiles
// Phase 3: bias + leaky + row L2 norm.  Layer 2 also re-zeroes its cursor slice
// (restores the g_cursor==0 invariant for the next launch/replay).
__global__ __launch_bounds__(256, 4)
void ngcf_fused(const float* __restrict__ out_ro, float* __restrict__ out, int layer) {
    extern __shared__ __align__(128) char sm[];
    const int tid  = threadIdx.x;
    const int row0 = blockIdx.x * 64;     // 3125 * 64 == NNODES exactly

    // stage W: linear copy of preconverted, pre-swizzled layer slab (fp16)
    {
        const uint4* gw = g_Wbf + layer * 1536;
        uint4* sw = (uint4*)(sm + SM_W);
        #pragma unroll 2
        for (int i = tid; i < 1536; i += 256) sw[i] = gw[i];
    }
    if (tid < 64) ((float*)(sm + SM_BIAS))[tid] = g_bias[layer * 64 + tid];

    // ---- phase 1 (merged): gather t1, build all three A blocks in fp16
    // chunks: [0..7] t1, [8..15] t1*e, [16..23] e
    {
        const float4* op = (const float4*)out_ro;
        #pragma unroll
        for (int j = 0; j < 4; j++) {
            int item = tid + 256 * j;          // 1024 items: (r, q)
            int r = item >> 4, q = item & 15;
            int n = row0 + r;
            int i0 = g_rowptr[n], i1 = g_rowptr[n + 1];
            const size_t colq = (size_t)layer * 16 + q;
            float4 acc = make_float4(0.f, 0.f, 0.f, 0.f);
            int i = i0;
            for (; i + 3 < i1; i += 4) {
                int2 p0 = g_csre[i],     p1 = g_csre[i + 1];
                int2 p2 = g_csre[i + 2], p3 = g_csre[i + 3];
                float4 v0 = op[(size_t)p0.x * 64 + colq];
                float4 v1 = op[(size_t)p1.x * 64 + colq];
                float4 v2 = op[(size_t)p2.x * 64 + colq];
                float4 v3 = op[(size_t)p3.x * 64 + colq];
                float w0 = __int_as_float(p0.y), w1 = __int_as_float(p1.y);
                float w2 = __int_as_float(p2.y), w3 = __int_as_float(p3.y);
                acc.x += w0 * v0.x + w1 * v1.x + w2 * v2.x + w3 * v3.x;
                acc.y += w0 * v0.y + w1 * v1.y + w2 * v2.y + w3 * v3.y;
                acc.z += w0 * v0.z + w1 * v1.z + w2 * v2.z + w3 * v3.z;
                acc.w += w0 * v0.w + w1 * v1.w + w2 * v2.w + w3 * v3.w;
            }
            for (; i < i1; i++) {
                int2 p = g_csre[i];
                float4 v = op[(size_t)p.x * 64 + colq];
                float w0 = __int_as_float(p.y);
                acc.x += w0 * v.x; acc.y += w0 * v.y;
                acc.z += w0 * v.z; acc.w += w0 * v.w;
            }
            // own e float4 and t1*e in full f32
            float4 ev = op[(size_t)n * 64 + colq];
            float4 t2 = make_float4(acc.x * ev.x, acc.y * ev.y,
                                    acc.z * ev.z, acc.w * ev.w);
            uint32_t half_off = (uint32_t)(q & 1) * 8;
            int c = q >> 1;
            *(uint2*)(sm + SM_A + swz_c(r, c) + half_off) =
                make_uint2(pack2h(acc.x, acc.y), pack2h(acc.z, acc.w));
            *(uint2*)(sm + SM_A + swz_c(r, 8 + c) + half_off) =
                make_uint2(pack2h(t2.x, t2.y), pack2h(t2.z, t2.w));
            *(uint2*)(sm + SM_A + swz_c(r, 16 + c) + half_off) =
                make_uint2(pack2h(ev.x, ev.y), pack2h(ev.z, ev.w));
        }
    }
    // restore cursor==0 invariant for the next launch (cursor is dead here:
    // only the CSR build uses it, and that finished before the layer kernels)
    if (layer == NLAYERS - 1 && tid < 64) g_cursor[row0 + tid] = 0;
    __syncthreads();

    // ---- phase 2: 8 warps = 2(m) x 4(n); warp tile 32(m) x 16(n); 12 k-steps
    const int wid = tid >> 5, lane = tid & 31;
    const int wm  = wid >> 2, wn = wid & 3;
    const uint32_t smA = (uint32_t)__cvta_generic_to_shared(sm) + SM_A;
    const uint32_t smW = (uint32_t)__cvta_generic_to_shared(sm) + SM_W;
    const uint32_t lr    = lane & 7;
    const uint32_t jlow  = (lane >> 3) & 1;
    const uint32_t jhigh = (lane >> 4) & 1;
    const uint32_t rowA0  = (uint32_t)wm * 32 + jlow * 8 + lr;
    const uint32_t baseA0 = smA + rowA0 * ROW_B;
    const uint32_t baseA1 = baseA0 + 16 * ROW_B;
    const uint32_t xA     = rowA0 & 7;
    const uint32_t rowW  = (uint32_t)wn * 16 + jhigh * 8 + lr;
    const uint32_t baseW = smW + rowW * ROW_B;
    const uint32_t xW    = rowW & 7;

    float acc[2][2][4];
    #pragma unroll
    for (int a = 0; a < 2; a++)
        #pragma unroll
        for (int b = 0; b < 2; b++)
            #pragma unroll
            for (int i = 0; i < 4; i++) acc[a][b][i] = 0.f;

    #pragma unroll
    for (int s = 0; s < 12; s++) {
        uint32_t cA = 2u * s + jhigh;
        uint32_t cW = 2u * s + jlow;
        uint32_t a0[4], a1[4], bw[4];
        ldm_x4(a0[0], a0[1], a0[2], a0[3], baseA0 + ((cA ^ xA) << 4));
        ldm_x4(a1[0], a1[1], a1[2], a1[3], baseA1 + ((cA ^ xA) << 4));
        ldm_x4(bw[0], bw[1], bw[2], bw[3], baseW  + ((cW ^ xW) << 4));
        #pragma unroll
        for (int nt = 0; nt < 2; nt++) {
            asm volatile(
                "mma.sync.aligned.m16n8k16.row.col.f32.f16.f16.f32 "
                "{%0,%1,%2,%3}, {%4,%5,%6,%7}, {%8,%9}, {%0,%1,%2,%3};"
                : "+f"(acc[0][nt][0]), "+f"(acc[0][nt][1]),
                  "+f"(acc[0][nt][2]), "+f"(acc[0][nt][3])
                : "r"(a0[0]), "r"(a0[1]), "r"(a0[2]), "r"(a0[3]),
                  "r"(bw[nt * 2]), "r"(bw[nt * 2 + 1]));
            asm volatile(
                "mma.sync.aligned.m16n8k16.row.col.f32.f16.f16.f32 "
                "{%0,%1,%2,%3}, {%4,%5,%6,%7}, {%8,%9}, {%0,%1,%2,%3};"
                : "+f"(acc[1][nt][0]), "+f"(acc[1][nt][1]),
                  "+f"(acc[1][nt][2]), "+f"(acc[1][nt][3])
                : "r"(a1[0]), "r"(a1[1]), "r"(a1[2]), "r"(a1[3]),
                  "r"(bw[nt * 2]), "r"(bw[nt * 2 + 1]));
        }
    }
    __syncthreads();   // A/W smem dead; reuse for f32 staging

    // ---- phase 3a: bias + leaky, frags -> smem [64][OPITCH]
    {
        float* smo = (float*)sm;
        const float* sbias = (const float*)(sm + SM_BIAS);
        const int g = lane >> 2, q = lane & 3;
        #pragma unroll
        for (int mt = 0; mt < 2; mt++) {
            #pragma unroll
            for (int nt = 0; nt < 2; nt++) {
                int col = wn * 16 + nt * 8 + q * 2;
                float b0 = sbias[col], b1 = sbias[col + 1];
                int r = wm * 32 + mt * 16 + g;
                float v0 = acc[mt][nt][0] + b0; v0 = (v0 >= 0.f) ? v0 : 0.01f * v0;
                float v1 = acc[mt][nt][1] + b1; v1 = (v1 >= 0.f) ? v1 : 0.01f * v1;
                float v2 = acc[mt][nt][2] + b0; v2 = (v2 >= 0.f) ? v2 : 0.01f * v2;
                float v3 = acc[mt][nt][3] + b1; v3 = (v3 >= 0.f) ? v3 : 0.01f * v3;
                *(float2*)(smo + r * OPITCH + col)       = make_float2(v0, v1);
                *(float2*)(smo + (r + 8) * OPITCH + col) = make_float2(v2, v3);
            }
        }
    }
    __syncthreads();

    // ---- phase 3b: L2-normalize + store: 4 threads per row, 16 cols each
    {
        const float* smo = (const float*)sm;
        int r = tid >> 2, h = tid & 3;
        int row = row0 + r;
        float4 v[4];
        float ssum = 0.f;
        #pragma unroll
        for (int i = 0; i < 4; i++) {
            v[i] = *(const float4*)(smo + r * OPITCH + h * 16 + i * 4);
            ssum += v[i].x * v[i].x + v[i].y * v[i].y + v[i].z * v[i].z + v[i].w * v[i].w;
        }
        ssum += __shfl_xor_sync(0xffffffffu, ssum, 1);
        ssum += __shfl_xor_sync(0xffffffffu, ssum, 2);
        float inv = 1.0f / fmaxf(sqrtf(ssum), 1e-12f);
        float4* o4 = (float4*)(out + (size_t)row * 256 + (size_t)(layer + 1) * 64 + h * 16);
        #pragma unroll
        for (int i = 0; i < 4; i++)
            o4[i] = make_float4(v[i].x * inv, v[i].y * inv, v[i].z * inv, v[i].w * inv);
    }
}

// ---------------------------------------------------------------- launch
extern "C" void kernel_launch(void* const* d_in, const int* in_sizes, int n_in,
                              void* d_out, int out_size) {
    const int*    edge_src = (const int*)d_in[0];
    const int*    edge_dst = (const int*)d_in[1];
    const float*  edge_w   = (const float*)d_in[2];
    const float4* u4       = (const float4*)d_in[3];
    const float4* i4       = (const float4*)d_in[4];
    const float*  Ws       = (const float*)d_in[5];
    const float*  bs       = (const float*)d_in[6];
    float*        out      = (float*)d_out;

    cudaFuncSetAttribute(ngcf_fused, cudaFuncAttributeMaxDynamicSharedMemorySize, SM_TOTAL);

    init_hist_kernel<<<(NNODES * 16 + 255) / 256, 256>>>(u4, i4, (float4*)out, edge_dst);
    scan1_kernel<<<NSCANB, 1024>>>();
    scan2_kernel<<<1, 256>>>();
    scan3_kernel<<<(NNODES + 255) / 256, 256>>>();
    fill_kernel<<<(NEDGES + 255) / 256, 256>>>(edge_src, edge_dst, edge_w);
    prep_w_kernel<<<3, 256>>>(Ws, bs);

    for (int l = 0; l < NLAYERS; l++) {
        ngcf_fused<<<NNODES / 64, 256, SM_TOTAL>>>(out, out, l);
    }
}